// round 8
// baseline (speedup 1.0000x reference)
#include <cuda_runtime.h>
#include <cuda_bf16.h>

// Problem constants (fixed by the reference)
#define B 8
#define N 2048
#define M 8192
#define C 64
#define NSEG 2048

#define CAP 32   // bucket capacity; multiplicity ~ Poisson(4), P(>=32) ~ 1e-26

// Scratch: per-(b,seg) counters and source-row index buckets.
// NOTE: gather relies on every g_bucket word being a valid row id in [0, M):
// zero-initialized at load, and only valid m values are ever stored.
__device__ int g_cnt_i[B * NSEG];          // 64 KB
__device__ int g_bucket[B * NSEG * CAP];   // 2 MB

// ---------------------------------------------------------------------------
// Kernel 1: bucket the source rows. One thread per (b, m).
// ---------------------------------------------------------------------------
__global__ void bucket_kernel(const int* __restrict__ index_source) {
    int T = blockIdx.x * blockDim.x + threadIdx.x;   // [0, B*M)
    if (T >= B * M) return;
    int b   = T >> 13;                               // M = 8192 = 2^13
    int seg = __ldg(&index_source[T]);
    int si  = (b << 11) + seg;                       // NSEG = 2048 = 2^11
    int pos = atomicAdd(&g_cnt_i[si], 1);
    if (pos < CAP) {
        g_bucket[(si << 5) + pos] = T & (M - 1);
    }
}

// ---------------------------------------------------------------------------
// Kernel 2: gather. One thread per (b, n, c4).
// All 8 leading source-row loads issue unconditionally (bucket entries are
// always valid row ids), so the only serial chain is seg -> bucket -> src.
// cnt only gates the accumulation, not the load issue.
// ---------------------------------------------------------------------------
__global__ void gather_kernel(const int* __restrict__ index_target,
                              const float* __restrict__ array_source,
                              float* __restrict__ out) {
    int t = blockIdx.x * blockDim.x + threadIdx.x;   // [0, B*N*16)
    if (t >= B * N * (C / 4)) return;
    int c4  = t & 15;
    int bn  = t >> 4;
    int b   = bn >> 11;                              // N = 2048 = 2^11
    int seg = __ldg(&index_target[bn]);
    int si  = (b << 11) + seg;

    const int4* bk = reinterpret_cast<const int4*>(&g_bucket[si << 5]);
    int4 e0 = __ldcg(&bk[0]);                        // entries 0..3 (broadcast)
    int4 e1 = __ldcg(&bk[1]);                        // entries 4..7
    int cnt = __ldcg(&g_cnt_i[si]);                  // parallel with bucket load

    const float4* src4 = reinterpret_cast<const float4*>(array_source);
    int src_base = (b << 13) * 16 + c4;              // b*M rows * 16 quads + c4

    // 8 independent, unconditional, coalesced row loads.
    float4 s0 = __ldg(&src4[src_base + e0.x * 16]);
    float4 s1 = __ldg(&src4[src_base + e0.y * 16]);
    float4 s2 = __ldg(&src4[src_base + e0.z * 16]);
    float4 s3 = __ldg(&src4[src_base + e0.w * 16]);
    float4 s4 = __ldg(&src4[src_base + e1.x * 16]);
    float4 s5 = __ldg(&src4[src_base + e1.y * 16]);
    float4 s6 = __ldg(&src4[src_base + e1.z * 16]);
    float4 s7 = __ldg(&src4[src_base + e1.w * 16]);

    float4 acc = make_float4(0.f, 0.f, 0.f, 0.f);
    if (cnt > 0) { acc.x += s0.x; acc.y += s0.y; acc.z += s0.z; acc.w += s0.w; }
    if (cnt > 1) { acc.x += s1.x; acc.y += s1.y; acc.z += s1.z; acc.w += s1.w; }
    if (cnt > 2) { acc.x += s2.x; acc.y += s2.y; acc.z += s2.z; acc.w += s2.w; }
    if (cnt > 3) { acc.x += s3.x; acc.y += s3.y; acc.z += s3.z; acc.w += s3.w; }
    if (cnt > 4) { acc.x += s4.x; acc.y += s4.y; acc.z += s4.z; acc.w += s4.w; }
    if (cnt > 5) { acc.x += s5.x; acc.y += s5.y; acc.z += s5.z; acc.w += s5.w; }
    if (cnt > 6) { acc.x += s6.x; acc.y += s6.y; acc.z += s6.z; acc.w += s6.w; }
    if (cnt > 7) { acc.x += s7.x; acc.y += s7.y; acc.z += s7.z; acc.w += s7.w; }

    // Rare tail: cnt > 8 (P ~ 2% per segment).
    int lim = min(cnt, CAP);
    if (lim > 8) {
#pragma unroll 1
        for (int i0 = 8; i0 < lim; i0 += 4) {
            int4 ms = __ldcg(&bk[i0 >> 2]);
            if (i0 + 0 < lim) {
                float4 s = __ldg(&src4[src_base + ms.x * 16]);
                acc.x += s.x; acc.y += s.y; acc.z += s.z; acc.w += s.w;
            }
            if (i0 + 1 < lim) {
                float4 s = __ldg(&src4[src_base + ms.y * 16]);
                acc.x += s.x; acc.y += s.y; acc.z += s.z; acc.w += s.w;
            }
            if (i0 + 2 < lim) {
                float4 s = __ldg(&src4[src_base + ms.z * 16]);
                acc.x += s.x; acc.y += s.y; acc.z += s.z; acc.w += s.w;
            }
            if (i0 + 3 < lim) {
                float4 s = __ldg(&src4[src_base + ms.w * 16]);
                acc.x += s.x; acc.y += s.y; acc.z += s.z; acc.w += s.w;
            }
        }
    }

    float inv = 1.0f / (1e-10f + (float)cnt);
    acc.x *= inv; acc.y *= inv; acc.z *= inv; acc.w *= inv;
    reinterpret_cast<float4*>(out)[t] = acc;
}

// ---------------------------------------------------------------------------
extern "C" void kernel_launch(void* const* d_in, const int* in_sizes, int n_in,
                              void* d_out, int out_size) {
    const int*   index_target = (const int*)d_in[0];   // [B, N, 1]
    const int*   index_source = (const int*)d_in[1];   // [B, M, 1]
    const float* array_source = (const float*)d_in[2]; // [B, M, C]
    float*       out          = (float*)d_out;         // [B, N, C]

    (void)in_sizes; (void)n_in; (void)out_size;

    void* cnt_ptr = nullptr;
    cudaGetSymbolAddress(&cnt_ptr, g_cnt_i);
    cudaMemsetAsync(cnt_ptr, 0, (size_t)B * NSEG * sizeof(int), 0);

    {
        int total = B * M;                             // 65,536
        int threads = 256;
        int blocks = (total + threads - 1) / threads;
        bucket_kernel<<<blocks, threads>>>(index_source);
    }
    {
        int total = B * N * (C / 4);                   // 262,144
        int threads = 256;
        int blocks = (total + threads - 1) / threads;
        gather_kernel<<<blocks, threads>>>(index_target, array_source, out);
    }
}